// round 13
// baseline (speedup 1.0000x reference)
#include <cuda_runtime.h>
#include <math_constants.h>
#include <cstdint>
#include <cstddef>

// Problem constants
#define HH 8
#define KD 64
#define VD 64
#define KNN 128
#define DM 512
#define FCD 2048
#define NB 4
#define SSQ 1024
#define EPS 1e-5f

// ---------------- scratch (single __device__ array, no allocations) ----------------
constexpr size_t OFF_GDEC = 0;
constexpr size_t OFF_GENC = OFF_GDEC + (size_t)SSQ * SSQ;
constexpr size_t OFF_K    = OFF_GENC + (size_t)SSQ * SSQ;
constexpr size_t OFF_V    = OFF_K   + (size_t)HH * NB * SSQ * KD;
constexpr size_t OFF_Q    = OFF_V   + (size_t)HH * NB * SSQ * VD;
constexpr size_t OFF_CTX  = OFF_Q   + (size_t)HH * NB * SSQ * KD;
constexpr size_t OFF_H    = OFF_CTX + (size_t)NB * SSQ * DM;
constexpr size_t OFF_H2   = OFF_H   + (size_t)NB * SSQ * DM;
constexpr size_t OFF_T    = OFF_H2  + (size_t)NB * SSQ * DM;
constexpr size_t OFF_ATT  = OFF_T   + (size_t)NB * SSQ * FCD;
constexpr size_t SCRATCH_TOTAL = OFF_ATT + (size_t)HH * NB * SSQ * SSQ;

__device__ float g_scratch[SCRATCH_TOTAL];

// ---------------- TF32 / mma / ldmatrix helpers ----------------
__device__ __forceinline__ uint32_t f2tf32(float f) {
    uint32_t o;
    asm("cvt.rna.tf32.f32 %0, %1;" : "=r"(o) : "f"(f));
    return o;
}

__device__ __forceinline__ void mma_tf32v(float c[4],
                                          uint32_t a0, uint32_t a1, uint32_t a2, uint32_t a3,
                                          uint32_t b0, uint32_t b1)
{
    asm volatile(
        "mma.sync.aligned.m16n8k8.row.col.f32.tf32.tf32.f32 "
        "{%0,%1,%2,%3}, {%4,%5,%6,%7}, {%8,%9}, {%0,%1,%2,%3};"
        : "+f"(c[0]), "+f"(c[1]), "+f"(c[2]), "+f"(c[3])
        : "r"(a0), "r"(a1), "r"(a2), "r"(a3),
          "r"(b0), "r"(b1));
}

__device__ __forceinline__ void ldsm4(uint32_t& d0, uint32_t& d1, uint32_t& d2, uint32_t& d3,
                                      uint32_t addr)
{
    asm volatile("ldmatrix.sync.aligned.m8n8.x4.shared.b16 {%0,%1,%2,%3}, [%4];"
                 : "=r"(d0), "=r"(d1), "=r"(d2), "=r"(d3) : "r"(addr));
}

// ---------------- batched TF32 tensor-core GEMM, SW128-swizzled smem + ldmatrix --------
// C = alpha*A@B(^T) [+bias][relu][+resid]
// Block tile 128(M) x NTILE(N), K-tile 32, 256 threads = 8 warps (4x2),
// warp tile 32 x NTILE/2, double-buffered dynamic smem.
// causal=1: skip blocks entirely above the diagonal.
template<int NTILE>
__global__ __launch_bounds__(256) void gemm_k(
    const float* __restrict__ A, const float* __restrict__ B, float* __restrict__ C,
    int Nc, int Kc, int ldc,
    long long sAo, long long sAi, long long sBo, long long sBi,
    long long sCo, long long sCi, int Bi,
    const float* __restrict__ bias, long long sBias,
    const float* __restrict__ resid, int ldr,
    float alpha, int transB, int relu, int causal)
{
    constexpr int AWORDS = 4096;            // 128 rows * 32 words per buffer
    constexpr int BWORDS = NTILE * 32;
    constexpr int LB = NTILE / 32;          // B loader units per thread (2 or 4)
    constexpr int NJ = NTILE / 16;          // n8-tiles per warp (4 or 8)
    constexpr int BQ = NTILE / 32;          // B ldsm.x4 per k8-step (2 or 4)

    extern __shared__ uint32_t smem_u[];
    uint32_t* AsB[2] = { smem_u, smem_u + AWORDS };
    uint32_t* BsB[2] = { smem_u + 2 * AWORDS, smem_u + 2 * AWORDS + BWORDS };

    int bn0 = blockIdx.x * NTILE;
    int bm0 = blockIdx.y * 128;
    if (causal && bn0 >= bm0 + 128) return;

    int z = blockIdx.z;
    int zo = z / Bi, zi = z - zo * Bi;
    A += (size_t)zo * sAo + (size_t)zi * sAi;
    B += (size_t)zo * sBo + (size_t)zi * sBi;
    C += (size_t)zo * sCo + (size_t)zi * sCi;
    const float* biasp = bias ? (bias + (size_t)zo * sBias) : nullptr;

    int t = threadIdx.x;
    int lane = t & 31, w = t >> 5;
    int wm = w >> 1, wn = w & 1;          // 4 x 2 warp grid
    int gid = lane >> 2, tg = lane & 3;

    // ---- loader mappings ----
    int a_row[4], aSt[4];
    #pragma unroll
    for (int i = 0; i < 4; i++) {
        int idx = t + i * 256;
        a_row[i] = idx >> 3; int kq = idx & 7;
        aSt[i] = a_row[i] * 32 + ((kq ^ (a_row[i] & 7)) << 2);
    }
    int bt_row[LB], btSt[LB];
    #pragma unroll
    for (int i = 0; i < LB; i++) {
        int idx = t + i * 256;
        bt_row[i] = idx >> 3; int kq = idx & 7;
        btSt[i] = bt_row[i] * 32 + ((kq ^ (bt_row[i] & 7)) << 2);
    }
    int bn_n[LB], bn_ks[LB], bnSt[LB];
    #pragma unroll
    for (int i = 0; i < LB; i++) {
        int idx = t + i * 256;
        bn_n[i] = idx & (NTILE - 1); bn_ks[i] = idx / NTILE;
        bnSt[i] = bn_n[i] * 32 + ((bn_ks[i] ^ (bn_n[i] & 7)) << 2);
    }

    // ---- auto-incrementing global fetch pointers ----
    const float4* paP[4];
    #pragma unroll
    for (int i = 0; i < 4; i++)
        paP[i] = (const float4*)(A + (size_t)(bm0 + a_row[i]) * Kc) + ((t + i * 256) & 7);
    const float4* pbtP[LB];
    const float*  pbnP[LB];
    if (transB) {
        #pragma unroll
        for (int i = 0; i < LB; i++)
            pbtP[i] = (const float4*)(B + (size_t)(bn0 + bt_row[i]) * Kc) + ((t + i * 256) & 7);
    } else {
        #pragma unroll
        for (int i = 0; i < LB; i++)
            pbnP[i] = B + (size_t)(bn_ks[i] * 4) * Nc + bn0 + bn_n[i];
    }
    int nc1 = Nc, nc2 = 2 * Nc, nc3 = 3 * Nc;
    long long bnStep = (long long)Nc * 32;

    // ---- fragment-load (ldmatrix) lane constants + precomputed smem offsets ----
    int r8 = lane & 7;
    int im = lane >> 3;
    int rowA0 = wm * 32 + r8 + 8 * (im & 1);
    int c1A = im >> 1;
    int rowB0 = wn * (NTILE / 2) + r8 + 8 * (im >> 1);
    int c1B = im & 1;

    uint32_t offA[4], offB[4];
    #pragma unroll
    for (int ks = 0; ks < 4; ks++) {
        offA[ks] = (uint32_t)(rowA0 * 128 + (((2 * ks + c1A) ^ r8) << 4));
        offB[ks] = (uint32_t)(rowB0 * 128 + (((2 * ks + c1B) ^ r8) << 4));
    }

    uint32_t sA[2], sB[2];
    sA[0] = (uint32_t)__cvta_generic_to_shared(AsB[0]);
    sA[1] = (uint32_t)__cvta_generic_to_shared(AsB[1]);
    sB[0] = (uint32_t)__cvta_generic_to_shared(BsB[0]);
    sB[1] = (uint32_t)__cvta_generic_to_shared(BsB[1]);

    float acc[2][NJ][4] = {};

    float4 pa[4]; float4 pbt[LB]; float pbn[LB][4];

    auto fetch_tile = [&]() {
        #pragma unroll
        for (int i = 0; i < 4; i++) { pa[i] = *paP[i]; paP[i] += 8; }
        if (transB) {
            #pragma unroll
            for (int i = 0; i < LB; i++) { pbt[i] = *pbtP[i]; pbtP[i] += 8; }
        } else {
            #pragma unroll
            for (int i = 0; i < LB; i++) {
                pbn[i][0] = pbnP[i][0];   pbn[i][1] = pbnP[i][nc1];
                pbn[i][2] = pbnP[i][nc2]; pbn[i][3] = pbnP[i][nc3];
                pbnP[i] += bnStep;
            }
        }
    };
    auto store_tile = [&](int buf) {
        uint32_t* Asb = AsB[buf];
        uint32_t* Bsb = BsB[buf];
        #pragma unroll
        for (int i = 0; i < 4; i++) {
            uint4 u;
            u.x = f2tf32(pa[i].x); u.y = f2tf32(pa[i].y);
            u.z = f2tf32(pa[i].z); u.w = f2tf32(pa[i].w);
            *(uint4*)&Asb[aSt[i]] = u;
        }
        if (transB) {
            #pragma unroll
            for (int i = 0; i < LB; i++) {
                uint4 u;
                u.x = f2tf32(pbt[i].x); u.y = f2tf32(pbt[i].y);
                u.z = f2tf32(pbt[i].z); u.w = f2tf32(pbt[i].w);
                *(uint4*)&Bsb[btSt[i]] = u;
            }
        } else {
            #pragma unroll
            for (int i = 0; i < LB; i++) {
                uint4 u;
                u.x = f2tf32(pbn[i][0]); u.y = f2tf32(pbn[i][1]);
                u.z = f2tf32(pbn[i][2]); u.w = f2tf32(pbn[i][3]);
                *(uint4*)&Bsb[bnSt[i]] = u;
            }
        }
    };

    // ---- prologue ----
    fetch_tile();
    store_tile(0);
    __syncthreads();

    int nT = Kc >> 5;
    int cur = 0;
    for (int tt = 0; tt < nT; tt++) {
        bool has = (tt + 1) < nT;
        if (has) fetch_tile();

        uint32_t baseA = sA[cur], baseB = sB[cur];
        #pragma unroll
        for (int ks = 0; ks < 4; ks++) {
            uint32_t aAddr = baseA + offA[ks];
            uint32_t bAddr = baseB + offB[ks];
            uint32_t af0[4], af1[4], bq[BQ][4];
            ldsm4(af0[0], af0[1], af0[2], af0[3], aAddr);
            ldsm4(af1[0], af1[1], af1[2], af1[3], aAddr + 2048);
            #pragma unroll
            for (int b = 0; b < BQ; b++)
                ldsm4(bq[b][0], bq[b][1], bq[b][2], bq[b][3], bAddr + (uint32_t)(b * 2048));
            #pragma unroll
            for (int nj = 0; nj < NJ; nj++) {
                uint32_t b0 = bq[nj >> 1][(nj & 1) * 2 + 0];
                uint32_t b1 = bq[nj >> 1][(nj & 1) * 2 + 1];
                mma_tf32v(acc[0][nj], af0[0], af0[1], af0[2], af0[3], b0, b1);
                mma_tf32v(acc[1][nj], af1[0], af1[1], af1[2], af1[3], b0, b1);
            }
        }

        if (has) {
            int nxt = cur ^ 1;
            store_tile(nxt);
            __syncthreads();
            cur = nxt;
        }
    }

    // ---- epilogue ----
    int mb = wm * 32, nb = wn * (NTILE / 2);
    #pragma unroll
    for (int mi = 0; mi < 2; mi++) {
        int r0 = bm0 + mb + mi * 16 + gid;
        #pragma unroll
        for (int nj = 0; nj < NJ; nj++) {
            int cc = bn0 + nb + nj * 8 + 2 * tg;
            float b0 = 0.f, b1 = 0.f;
            if (biasp) { b0 = biasp[cc]; b1 = biasp[cc + 1]; }
            #pragma unroll
            for (int half = 0; half < 2; half++) {
                int row = r0 + half * 8;
                float vx = acc[mi][nj][half * 2 + 0] * alpha + b0;
                float vy = acc[mi][nj][half * 2 + 1] * alpha + b1;
                if (relu) { vx = fmaxf(vx, 0.f); vy = fmaxf(vy, 0.f); }
                if (resid) {
                    float2 r = *(const float2*)&resid[(size_t)row * ldr + cc];
                    vx += r.x; vy += r.y;
                }
                float2 o; o.x = vx; o.y = vy;
                *(float2*)&C[(size_t)row * ldc + cc] = o;
            }
        }
    }
}

// ---------------- row softmax (graph preprocessing), rows of length SSQ ----------------
__global__ __launch_bounds__(256) void row_softmax_k(const float* __restrict__ in,
                                                     float* __restrict__ out)
{
    __shared__ float sh[8];
    int row = blockIdx.x;
    int t = threadIdx.x;
    int lane = t & 31, w = t >> 5;
    const float* rin = in + (size_t)row * SSQ;
    float* rout = out + (size_t)row * SSQ;

    float4 v4 = *(const float4*)&rin[t * 4];
    float v[4] = {v4.x, v4.y, v4.z, v4.w};

    float m = fmaxf(fmaxf(v[0], v[1]), fmaxf(v[2], v[3]));
    #pragma unroll
    for (int o = 16; o; o >>= 1) m = fmaxf(m, __shfl_xor_sync(0xffffffffu, m, o));
    if (lane == 0) sh[w] = m;
    __syncthreads();
    m = sh[0];
    #pragma unroll
    for (int i = 1; i < 8; i++) m = fmaxf(m, sh[i]);
    __syncthreads();

    float e[4]; float s = 0.f;
    #pragma unroll
    for (int i = 0; i < 4; i++) { e[i] = expf(v[i] - m); s += e[i]; }
    #pragma unroll
    for (int o = 16; o; o >>= 1) s += __shfl_xor_sync(0xffffffffu, s, o);
    if (lane == 0) sh[w] = s;
    __syncthreads();
    s = 0.f;
    #pragma unroll
    for (int i = 0; i < 8; i++) s += sh[i];
    float inv = 1.0f / s;
    float4 o4;
    o4.x = e[0] * inv; o4.y = e[1] * inv; o4.z = e[2] * inv; o4.w = e[3] * inv;
    *(float4*)&rout[t * 4] = o4;
}

// ---------------- fused: causal mask + exact top-KNN + softmax + graph blend ----------
// One WARP per attention row: keys in 32 regs, REDUX reductions, zero barriers.
__device__ __forceinline__ unsigned f2key(float f) {
    unsigned u = __float_as_uint(f);
    return (u & 0x80000000u) ? ~u : (u | 0x80000000u);
}
__device__ __forceinline__ float key2f(unsigned k) {
    unsigned u = (k & 0x80000000u) ? (k & 0x7fffffffu) : ~k;
    return __uint_as_float(u);
}

__global__ __launch_bounds__(256) void attn_post_k(float* __restrict__ att,
                                                   const float* __restrict__ graph,
                                                   int masked, float gw)
{
    int wid = threadIdx.x >> 5, lane = threadIdx.x & 31;
    int rowIdx = blockIdx.x * 8 + wid;            // [0, HH*NB*SSQ)
    int q = rowIdx & (SSQ - 1);
    float* row = att + (size_t)rowIdx * SSQ;
    const float* grow = graph + (size_t)q * SSQ;
    int L = masked ? (q + 1) : SSQ;
    int lb = lane * 4;

    unsigned key[32];
    #pragma unroll
    for (int i = 0; i < 8; i++) {
        int pos = i * 128 + lb;
        float4 v4 = *(const float4*)&row[pos];
        key[i * 4 + 0] = (pos + 0 < L) ? f2key(v4.x) : 0u;
        key[i * 4 + 1] = (pos + 1 < L) ? f2key(v4.y) : 0u;
        key[i * 4 + 2] = (pos + 2 < L) ? f2key(v4.z) : 0u;
        key[i * 4 + 3] = (pos + 3 < L) ? f2key(v4.w) : 0u;
    }

    // warp max key (== key of max valid value, by monotonicity; L>=1 always)
    unsigned kmax = 0;
    #pragma unroll
    for (int i = 0; i < 32; i++) kmax = max(kmax, key[i]);
    kmax = __reduce_max_sync(0xffffffffu, kmax);
    float m = key2f(kmax);

    // exact top-KNN threshold: binary search on key bits, early exit at count==KNN
    unsigned threshKey = 0;
    if (L > KNN) {
        unsigned lo = 0u, hi = kmax;
        while (lo < hi) {
            unsigned mid = (unsigned)((((unsigned long long)lo + (unsigned long long)hi + 1ull)) >> 1);
            unsigned c = 0;
            #pragma unroll
            for (int i = 0; i < 32; i++) c += (key[i] >= mid) ? 1u : 0u;
            c = __reduce_add_sync(0xffffffffu, c);
            if (c == KNN) { lo = mid; break; }    // {key>=mid} == exact top-KNN set
            if (c > KNN) lo = mid; else hi = mid - 1u;
        }
        threshKey = lo;
    }

    // softmax denominator over kept (values recovered bit-exactly from keys)
    bool noTrunc = (L <= KNN);
    float s = 0.f;
    #pragma unroll
    for (int i = 0; i < 8; i++) {
        int pos = i * 128 + lb;
        #pragma unroll
        for (int j = 0; j < 4; j++) {
            unsigned k = key[i * 4 + j];
            bool kept = (pos + j < L) && (noTrunc || k >= threshKey);
            if (kept) s += expf(key2f(k) - m);
        }
    }
    #pragma unroll
    for (int o = 16; o; o >>= 1) s += __shfl_xor_sync(0xffffffffu, s, o);
    float inv = 1.0f / s;
    float og = 1.0f - gw;

    // blend + store
    #pragma unroll
    for (int i = 0; i < 8; i++) {
        int pos = i * 128 + lb;
        float4 g4 = *(const float4*)&grow[pos];
        float gv[4] = {g4.x, g4.y, g4.z, g4.w};
        float4 o4;
        float* ov = (float*)&o4;
        #pragma unroll
        for (int j = 0; j < 4; j++) {
            unsigned k = key[i * 4 + j];
            bool kept = (pos + j < L) && (noTrunc || k >= threshKey);
            float e = kept ? expf(key2f(k) - m) : 0.f;
            ov[j] = gw * gv[j] + og * (e * inv);
        }
        *(float4*)&row[pos] = o4;
    }
}

// ---------------- LayerNorm over rows of DM=512 (elementwise_affine=False) ----------------
__global__ __launch_bounds__(128) void layernorm_k(const float* __restrict__ in,
                                                   float* __restrict__ out)
{
    __shared__ float sh[4];
    int row = blockIdx.x;
    int t = threadIdx.x;
    int lane = t & 31, w = t >> 5;
    const float* rin = in + (size_t)row * DM;
    float* rout = out + (size_t)row * DM;

    float4 v4 = *(const float4*)&rin[t * 4];
    float v[4] = {v4.x, v4.y, v4.z, v4.w};

    float s = v[0] + v[1] + v[2] + v[3];
    #pragma unroll
    for (int o = 16; o; o >>= 1) s += __shfl_xor_sync(0xffffffffu, s, o);
    if (lane == 0) sh[w] = s;
    __syncthreads();
    s = sh[0] + sh[1] + sh[2] + sh[3];
    float mean = s * (1.0f / DM);
    __syncthreads();

    float sq = 0.f;
    #pragma unroll
    for (int i = 0; i < 4; i++) { float d = v[i] - mean; sq += d * d; }
    #pragma unroll
    for (int o = 16; o; o >>= 1) sq += __shfl_xor_sync(0xffffffffu, sq, o);
    if (lane == 0) sh[w] = sq;
    __syncthreads();
    sq = sh[0] + sh[1] + sh[2] + sh[3];
    float var = sq * (1.0f / DM);
    float inv = rsqrtf(var + EPS);

    float4 o4;
    o4.x = (v[0] - mean) * inv; o4.y = (v[1] - mean) * inv;
    o4.z = (v[2] - mean) * inv; o4.w = (v[3] - mean) * inv;
    *(float4*)&rout[t * 4] = o4;
}

// ---------------- host-side helpers ----------------
template<int NTILE>
static inline void gemm_t(const float* A, const float* B, float* C,
                          int M, int Nc, int Kc, int ldc,
                          long long sAo, long long sAi, long long sBo, long long sBi,
                          long long sCo, long long sCi, int Bo, int Bi,
                          const float* bias, long long sBias,
                          const float* resid, int ldr,
                          float alpha, int transB, int relu, int causal = 0)
{
    dim3 grid(Nc / NTILE, M / 128, Bo * Bi), block(256);
    size_t smem = (2 * 4096 + 2 * NTILE * 32) * sizeof(uint32_t);
    gemm_k<NTILE><<<grid, block, smem>>>(A, B, C, Nc, Kc, ldc, sAo, sAi, sBo, sBi,
                                         sCo, sCi, Bi, bias, sBias, resid, ldr,
                                         alpha, transB, relu, causal);
}

extern "C" void kernel_launch(void* const* d_in, const int* in_sizes, int n_in,
                              void* d_out, int out_size)
{
    (void)in_sizes; (void)n_in; (void)out_size;
    const float* z        = (const float*)d_in[0];
    const float* y        = (const float*)d_in[1];
    const float* graphDec = (const float*)d_in[2];
    const float* graphEnc = (const float*)d_in[3];
    const float* dec_Wk   = (const float*)d_in[4];
    const float* dec_bk   = (const float*)d_in[5];
    const float* dec_Wv   = (const float*)d_in[6];
    const float* dec_bv   = (const float*)d_in[7];
    const float* dec_Wo   = (const float*)d_in[8];
    const float* dec_bo   = (const float*)d_in[9];
    const float* enc_Wk   = (const float*)d_in[10];
    const float* enc_bk   = (const float*)d_in[11];
    const float* enc_Wq   = (const float*)d_in[12];
    const float* enc_bq   = (const float*)d_in[13];
    const float* enc_Wv   = (const float*)d_in[14];
    const float* enc_bv   = (const float*)d_in[15];
    const float* enc_Wo   = (const float*)d_in[16];
    const float* enc_bo   = (const float*)d_in[17];
    const float* fc_W1    = (const float*)d_in[18];
    const float* fc_b1    = (const float*)d_in[19];
    const float* fc_W2    = (const float*)d_in[20];
    const float* fc_b2    = (const float*)d_in[21];
    float* out = (float*)d_out;

    // allow 64KB dynamic smem for the wide-tile instantiation (host-side, idempotent)
    cudaFuncSetAttribute(gemm_k<128>, cudaFuncAttributeMaxDynamicSharedMemorySize, 66560);

    float* sc = nullptr;
    cudaGetSymbolAddress((void**)&sc, g_scratch);
    float* gdec = sc + OFF_GDEC;
    float* genc = sc + OFF_GENC;
    float* gK   = sc + OFF_K;
    float* gV   = sc + OFF_V;
    float* gQ   = sc + OFF_Q;
    float* gCtx = sc + OFF_CTX;
    float* gH   = sc + OFF_H;
    float* gH2  = sc + OFF_H2;
    float* gT   = sc + OFF_T;
    float* gAtt = sc + OFF_ATT;

    const int M = NB * SSQ;               // 4096
    const long long sKh = (long long)NB * SSQ * KD;  // per-head stride in K/V/Q
    const long long sKn = (long long)SSQ * KD;       // per-batch stride
    const long long sAh = (long long)NB * SSQ * SSQ; // att per-head
    const long long sAn = (long long)SSQ * SSQ;      // att per-batch
    const float inv_scale = 0.125f;       // 1/sqrt(64)
    const int ROWS = HH * NB * SSQ;       // 32768 attention rows

    // 0) graph row-softmax
    row_softmax_k<<<SSQ, 256>>>(graphDec, gdec);
    row_softmax_k<<<SSQ, 256>>>(graphEnc, genc);

    // ---------- stage 1: masked decoder self-attention on y ----------
    gemm_t<64>(y, dec_Wk, gK, M, KD, DM, KD, 0, 0, (long long)DM * KD, 0, sKh, 0, HH, 1,
               dec_bk, KD, nullptr, 0, 1.0f, 0, 0);
    gemm_t<64>(y, dec_Wv, gV, M, VD, DM, VD, 0, 0, (long long)DM * VD, 0, sKh, 0, HH, 1,
               dec_bv, VD, nullptr, 0, 1.0f, 0, 0);
    gemm_t<128>(gK, gK, gAtt, SSQ, SSQ, KD, SSQ, sKh, sKn, sKh, sKn, sAh, sAn, HH, NB,
                nullptr, 0, nullptr, 0, inv_scale, 1, 0, 1 /*causal skip*/);
    attn_post_k<<<ROWS / 8, 256>>>(gAtt, gdec, 1, 0.5f);
    gemm_t<64>(gAtt, gV, gCtx, SSQ, VD, SSQ, DM, sAh, sAn, sKh, sKn, (long long)VD,
               (long long)SSQ * DM, HH, NB, nullptr, 0, nullptr, 0, 1.0f, 0, 0);
    gemm_t<128>(gCtx, dec_Wo, gH, M, DM, DM, DM, 0, 0, 0, 0, 0, 0, 1, 1,
                dec_bo, 0, y, DM, 1.0f, 0, 0);
    layernorm_k<<<M, 128>>>(gH, gH);      // gH = h

    // ---------- stage 2: encoder-decoder attention (K,V from z, Q from h) ----------
    gemm_t<64>(z, enc_Wk, gK, M, KD, DM, KD, 0, 0, (long long)DM * KD, 0, sKh, 0, HH, 1,
               enc_bk, KD, nullptr, 0, 1.0f, 0, 0);
    gemm_t<64>(z, enc_Wv, gV, M, VD, DM, VD, 0, 0, (long long)DM * VD, 0, sKh, 0, HH, 1,
               enc_bv, VD, nullptr, 0, 1.0f, 0, 0);
    gemm_t<64>(gH, enc_Wq, gQ, M, KD, DM, KD, 0, 0, (long long)DM * KD, 0, sKh, 0, HH, 1,
               enc_bq, KD, nullptr, 0, 1.0f, 0, 0);
    gemm_t<128>(gQ, gK, gAtt, SSQ, SSQ, KD, SSQ, sKh, sKn, sKh, sKn, sAh, sAn, HH, NB,
                nullptr, 0, nullptr, 0, inv_scale, 1, 0);
    attn_post_k<<<ROWS / 8, 256>>>(gAtt, genc, 0, 0.5f);
    gemm_t<64>(gAtt, gV, gCtx, SSQ, VD, SSQ, DM, sAh, sAn, sKh, sKn, (long long)VD,
               (long long)SSQ * DM, HH, NB, nullptr, 0, nullptr, 0, 1.0f, 0, 0);
    gemm_t<128>(gCtx, enc_Wo, gH2, M, DM, DM, DM, 0, 0, 0, 0, 0, 0, 1, 1,
                enc_bo, 0, gH, DM, 1.0f, 0, 0);
    layernorm_k<<<M, 128>>>(gH2, gH2);    // gH2 = h2

    // ---------- stage 3: MLP ----------
    gemm_t<128>(gH2, fc_W1, gT, M, FCD, DM, FCD, 0, 0, 0, 0, 0, 0, 1, 1,
                fc_b1, 0, nullptr, 0, 1.0f, 0, 1);                 // relu
    gemm_t<128>(gT, fc_W2, gH, M, DM, FCD, DM, 0, 0, 0, 0, 0, 0, 1, 1,
                fc_b2, 0, gH2, DM, 1.0f, 0, 0);                    // + residual h2
    layernorm_k<<<M, 128>>>(gH, out);
}

// round 14
// speedup vs baseline: 1.0908x; 1.0908x over previous
#include <cuda_runtime.h>
#include <math_constants.h>
#include <cstdint>
#include <cstddef>

// Problem constants
#define HH 8
#define KD 64
#define VD 64
#define KNN 128
#define DM 512
#define FCD 2048
#define NB 4
#define SSQ 1024
#define EPS 1e-5f

// ---------------- scratch (single __device__ array, no allocations) ----------------
constexpr size_t OFF_GDEC = 0;
constexpr size_t OFF_GENC = OFF_GDEC + (size_t)SSQ * SSQ;
constexpr size_t OFF_K    = OFF_GENC + (size_t)SSQ * SSQ;
constexpr size_t OFF_V    = OFF_K   + (size_t)HH * NB * SSQ * KD;
constexpr size_t OFF_Q    = OFF_V   + (size_t)HH * NB * SSQ * VD;
constexpr size_t OFF_CTX  = OFF_Q   + (size_t)HH * NB * SSQ * KD;
constexpr size_t OFF_H    = OFF_CTX + (size_t)NB * SSQ * DM;
constexpr size_t OFF_H2   = OFF_H   + (size_t)NB * SSQ * DM;
constexpr size_t OFF_T    = OFF_H2  + (size_t)NB * SSQ * DM;
constexpr size_t OFF_ATT  = OFF_T   + (size_t)NB * SSQ * FCD;
constexpr size_t SCRATCH_TOTAL = OFF_ATT + (size_t)HH * NB * SSQ * SSQ;

__device__ float g_scratch[SCRATCH_TOTAL];

// ---------------- TF32 / mma / ldmatrix helpers ----------------
__device__ __forceinline__ uint32_t f2tf32(float f) {
    uint32_t o;
    asm("cvt.rna.tf32.f32 %0, %1;" : "=r"(o) : "f"(f));
    return o;
}

__device__ __forceinline__ void mma_tf32v(float c[4],
                                          uint32_t a0, uint32_t a1, uint32_t a2, uint32_t a3,
                                          uint32_t b0, uint32_t b1)
{
    asm volatile(
        "mma.sync.aligned.m16n8k8.row.col.f32.tf32.tf32.f32 "
        "{%0,%1,%2,%3}, {%4,%5,%6,%7}, {%8,%9}, {%0,%1,%2,%3};"
        : "+f"(c[0]), "+f"(c[1]), "+f"(c[2]), "+f"(c[3])
        : "r"(a0), "r"(a1), "r"(a2), "r"(a3),
          "r"(b0), "r"(b1));
}

__device__ __forceinline__ void ldsm4(uint32_t& d0, uint32_t& d1, uint32_t& d2, uint32_t& d3,
                                      uint32_t addr)
{
    asm volatile("ldmatrix.sync.aligned.m8n8.x4.shared.b16 {%0,%1,%2,%3}, [%4];"
                 : "=r"(d0), "=r"(d1), "=r"(d2), "=r"(d3) : "r"(addr));
}

// ---------------- batched TF32 tensor-core GEMM, SW128-swizzled smem + ldmatrix --------
// C = alpha*A@B(^T) [+bias][relu][+resid]
// Block tile 128(M) x NTILE(N), K-tile 32, 256 threads = 8 warps (4x2),
// warp tile 32 x NTILE/2, double-buffered dynamic smem.
// MINCTA: min blocks/SM for launch_bounds. NTILE=64 -> 2 (regs<=128, proven),
// NTILE=128 -> 1 (regs free up to 255, NO SPILLS for the 64-reg accumulator file).
// causal=1: skip blocks entirely above the diagonal.
template<int NTILE, int MINCTA>
__global__ __launch_bounds__(256, MINCTA) void gemm_k(
    const float* __restrict__ A, const float* __restrict__ B, float* __restrict__ C,
    int Nc, int Kc, int ldc,
    long long sAo, long long sAi, long long sBo, long long sBi,
    long long sCo, long long sCi, int Bi,
    const float* __restrict__ bias, long long sBias,
    const float* __restrict__ resid, int ldr,
    float alpha, int transB, int relu, int causal)
{
    constexpr int AWORDS = 4096;            // 128 rows * 32 words per buffer
    constexpr int BWORDS = NTILE * 32;
    constexpr int LB = NTILE / 32;          // B loader units per thread (2 or 4)
    constexpr int NJ = NTILE / 16;          // n8-tiles per warp (4 or 8)
    constexpr int BQ = NTILE / 32;          // B ldsm.x4 per k8-step (2 or 4)

    extern __shared__ uint32_t smem_u[];
    uint32_t* AsB[2] = { smem_u, smem_u + AWORDS };
    uint32_t* BsB[2] = { smem_u + 2 * AWORDS, smem_u + 2 * AWORDS + BWORDS };

    int bn0 = blockIdx.x * NTILE;
    int bm0 = blockIdx.y * 128;
    if (causal && bn0 >= bm0 + 128) return;

    int z = blockIdx.z;
    int zo = z / Bi, zi = z - zo * Bi;
    A += (size_t)zo * sAo + (size_t)zi * sAi;
    B += (size_t)zo * sBo + (size_t)zi * sBi;
    C += (size_t)zo * sCo + (size_t)zi * sCi;
    const float* biasp = bias ? (bias + (size_t)zo * sBias) : nullptr;

    int t = threadIdx.x;
    int lane = t & 31, w = t >> 5;
    int wm = w >> 1, wn = w & 1;          // 4 x 2 warp grid
    int gid = lane >> 2, tg = lane & 3;

    // ---- loader mappings ----
    int a_row[4], aSt[4];
    #pragma unroll
    for (int i = 0; i < 4; i++) {
        int idx = t + i * 256;
        a_row[i] = idx >> 3; int kq = idx & 7;
        aSt[i] = a_row[i] * 32 + ((kq ^ (a_row[i] & 7)) << 2);
    }
    int bt_row[LB], btSt[LB];
    #pragma unroll
    for (int i = 0; i < LB; i++) {
        int idx = t + i * 256;
        bt_row[i] = idx >> 3; int kq = idx & 7;
        btSt[i] = bt_row[i] * 32 + ((kq ^ (bt_row[i] & 7)) << 2);
    }
    int bn_n[LB], bn_ks[LB], bnSt[LB];
    #pragma unroll
    for (int i = 0; i < LB; i++) {
        int idx = t + i * 256;
        bn_n[i] = idx & (NTILE - 1); bn_ks[i] = idx / NTILE;
        bnSt[i] = bn_n[i] * 32 + ((bn_ks[i] ^ (bn_n[i] & 7)) << 2);
    }

    // ---- auto-incrementing global fetch pointers ----
    const float4* paP[4];
    #pragma unroll
    for (int i = 0; i < 4; i++)
        paP[i] = (const float4*)(A + (size_t)(bm0 + a_row[i]) * Kc) + ((t + i * 256) & 7);
    const float4* pbtP[LB];
    const float*  pbnP[LB];
    if (transB) {
        #pragma unroll
        for (int i = 0; i < LB; i++)
            pbtP[i] = (const float4*)(B + (size_t)(bn0 + bt_row[i]) * Kc) + ((t + i * 256) & 7);
    } else {
        #pragma unroll
        for (int i = 0; i < LB; i++)
            pbnP[i] = B + (size_t)(bn_ks[i] * 4) * Nc + bn0 + bn_n[i];
    }
    int nc1 = Nc, nc2 = 2 * Nc, nc3 = 3 * Nc;
    long long bnStep = (long long)Nc * 32;

    // ---- fragment-load (ldmatrix) lane constants + precomputed smem offsets ----
    int r8 = lane & 7;
    int im = lane >> 3;
    int rowA0 = wm * 32 + r8 + 8 * (im & 1);
    int c1A = im >> 1;
    int rowB0 = wn * (NTILE / 2) + r8 + 8 * (im >> 1);
    int c1B = im & 1;

    uint32_t offA[4], offB[4];
    #pragma unroll
    for (int ks = 0; ks < 4; ks++) {
        offA[ks] = (uint32_t)(rowA0 * 128 + (((2 * ks + c1A) ^ r8) << 4));
        offB[ks] = (uint32_t)(rowB0 * 128 + (((2 * ks + c1B) ^ r8) << 4));
    }

    uint32_t sA[2], sB[2];
    sA[0] = (uint32_t)__cvta_generic_to_shared(AsB[0]);
    sA[1] = (uint32_t)__cvta_generic_to_shared(AsB[1]);
    sB[0] = (uint32_t)__cvta_generic_to_shared(BsB[0]);
    sB[1] = (uint32_t)__cvta_generic_to_shared(BsB[1]);

    float acc[2][NJ][4] = {};

    float4 pa[4]; float4 pbt[LB]; float pbn[LB][4];

    auto fetch_tile = [&]() {
        #pragma unroll
        for (int i = 0; i < 4; i++) { pa[i] = *paP[i]; paP[i] += 8; }
        if (transB) {
            #pragma unroll
            for (int i = 0; i < LB; i++) { pbt[i] = *pbtP[i]; pbtP[i] += 8; }
        } else {
            #pragma unroll
            for (int i = 0; i < LB; i++) {
                pbn[i][0] = pbnP[i][0];   pbn[i][1] = pbnP[i][nc1];
                pbn[i][2] = pbnP[i][nc2]; pbn[i][3] = pbnP[i][nc3];
                pbnP[i] += bnStep;
            }
        }
    };
    auto store_tile = [&](int buf) {
        uint32_t* Asb = AsB[buf];
        uint32_t* Bsb = BsB[buf];
        #pragma unroll
        for (int i = 0; i < 4; i++) {
            uint4 u;
            u.x = f2tf32(pa[i].x); u.y = f2tf32(pa[i].y);
            u.z = f2tf32(pa[i].z); u.w = f2tf32(pa[i].w);
            *(uint4*)&Asb[aSt[i]] = u;
        }
        if (transB) {
            #pragma unroll
            for (int i = 0; i < LB; i++) {
                uint4 u;
                u.x = f2tf32(pbt[i].x); u.y = f2tf32(pbt[i].y);
                u.z = f2tf32(pbt[i].z); u.w = f2tf32(pbt[i].w);
                *(uint4*)&Bsb[btSt[i]] = u;
            }
        } else {
            #pragma unroll
            for (int i = 0; i < LB; i++) {
                uint4 u;
                u.x = f2tf32(pbn[i][0]); u.y = f2tf32(pbn[i][1]);
                u.z = f2tf32(pbn[i][2]); u.w = f2tf32(pbn[i][3]);
                *(uint4*)&Bsb[bnSt[i]] = u;
            }
        }
    };

    // ---- prologue ----
    fetch_tile();
    store_tile(0);
    __syncthreads();

    int nT = Kc >> 5;
    int cur = 0;
    for (int tt = 0; tt < nT; tt++) {
        bool has = (tt + 1) < nT;
        if (has) fetch_tile();

        uint32_t baseA = sA[cur], baseB = sB[cur];
        #pragma unroll
        for (int ks = 0; ks < 4; ks++) {
            uint32_t aAddr = baseA + offA[ks];
            uint32_t bAddr = baseB + offB[ks];
            uint32_t af0[4], af1[4], bq[BQ][4];
            ldsm4(af0[0], af0[1], af0[2], af0[3], aAddr);
            ldsm4(af1[0], af1[1], af1[2], af1[3], aAddr + 2048);
            #pragma unroll
            for (int b = 0; b < BQ; b++)
                ldsm4(bq[b][0], bq[b][1], bq[b][2], bq[b][3], bAddr + (uint32_t)(b * 2048));
            #pragma unroll
            for (int nj = 0; nj < NJ; nj++) {
                uint32_t b0 = bq[nj >> 1][(nj & 1) * 2 + 0];
                uint32_t b1 = bq[nj >> 1][(nj & 1) * 2 + 1];
                mma_tf32v(acc[0][nj], af0[0], af0[1], af0[2], af0[3], b0, b1);
                mma_tf32v(acc[1][nj], af1[0], af1[1], af1[2], af1[3], b0, b1);
            }
        }

        if (has) {
            int nxt = cur ^ 1;
            store_tile(nxt);
            __syncthreads();
            cur = nxt;
        }
    }

    // ---- epilogue ----
    int mb = wm * 32, nb = wn * (NTILE / 2);
    #pragma unroll
    for (int mi = 0; mi < 2; mi++) {
        int r0 = bm0 + mb + mi * 16 + gid;
        #pragma unroll
        for (int nj = 0; nj < NJ; nj++) {
            int cc = bn0 + nb + nj * 8 + 2 * tg;
            float b0 = 0.f, b1 = 0.f;
            if (biasp) { b0 = biasp[cc]; b1 = biasp[cc + 1]; }
            #pragma unroll
            for (int half = 0; half < 2; half++) {
                int row = r0 + half * 8;
                float vx = acc[mi][nj][half * 2 + 0] * alpha + b0;
                float vy = acc[mi][nj][half * 2 + 1] * alpha + b1;
                if (relu) { vx = fmaxf(vx, 0.f); vy = fmaxf(vy, 0.f); }
                if (resid) {
                    float2 r = *(const float2*)&resid[(size_t)row * ldr + cc];
                    vx += r.x; vy += r.y;
                }
                float2 o; o.x = vx; o.y = vy;
                *(float2*)&C[(size_t)row * ldc + cc] = o;
            }
        }
    }
}

// ---------------- row softmax (graph preprocessing), rows of length SSQ ----------------
__global__ __launch_bounds__(256) void row_softmax_k(const float* __restrict__ in,
                                                     float* __restrict__ out)
{
    __shared__ float sh[8];
    int row = blockIdx.x;
    int t = threadIdx.x;
    int lane = t & 31, w = t >> 5;
    const float* rin = in + (size_t)row * SSQ;
    float* rout = out + (size_t)row * SSQ;

    float4 v4 = *(const float4*)&rin[t * 4];
    float v[4] = {v4.x, v4.y, v4.z, v4.w};

    float m = fmaxf(fmaxf(v[0], v[1]), fmaxf(v[2], v[3]));
    #pragma unroll
    for (int o = 16; o; o >>= 1) m = fmaxf(m, __shfl_xor_sync(0xffffffffu, m, o));
    if (lane == 0) sh[w] = m;
    __syncthreads();
    m = sh[0];
    #pragma unroll
    for (int i = 1; i < 8; i++) m = fmaxf(m, sh[i]);
    __syncthreads();

    float e[4]; float s = 0.f;
    #pragma unroll
    for (int i = 0; i < 4; i++) { e[i] = expf(v[i] - m); s += e[i]; }
    #pragma unroll
    for (int o = 16; o; o >>= 1) s += __shfl_xor_sync(0xffffffffu, s, o);
    if (lane == 0) sh[w] = s;
    __syncthreads();
    s = 0.f;
    #pragma unroll
    for (int i = 0; i < 8; i++) s += sh[i];
    float inv = 1.0f / s;
    float4 o4;
    o4.x = e[0] * inv; o4.y = e[1] * inv; o4.z = e[2] * inv; o4.w = e[3] * inv;
    *(float4*)&rout[t * 4] = o4;
}

// ---------------- fused: causal mask + exact top-KNN + softmax + graph blend ----------
// One WARP per attention row: keys in 32 regs, REDUX reductions, zero barriers.
__device__ __forceinline__ unsigned f2key(float f) {
    unsigned u = __float_as_uint(f);
    return (u & 0x80000000u) ? ~u : (u | 0x80000000u);
}
__device__ __forceinline__ float key2f(unsigned k) {
    unsigned u = (k & 0x80000000u) ? (k & 0x7fffffffu) : ~k;
    return __uint_as_float(u);
}

__global__ __launch_bounds__(256) void attn_post_k(float* __restrict__ att,
                                                   const float* __restrict__ graph,
                                                   int masked, float gw)
{
    int wid = threadIdx.x >> 5, lane = threadIdx.x & 31;
    int rowIdx = blockIdx.x * 8 + wid;            // [0, HH*NB*SSQ)
    int q = rowIdx & (SSQ - 1);
    float* row = att + (size_t)rowIdx * SSQ;
    const float* grow = graph + (size_t)q * SSQ;
    int L = masked ? (q + 1) : SSQ;
    int lb = lane * 4;

    unsigned key[32];
    #pragma unroll
    for (int i = 0; i < 8; i++) {
        int pos = i * 128 + lb;
        float4 v4 = *(const float4*)&row[pos];
        key[i * 4 + 0] = (pos + 0 < L) ? f2key(v4.x) : 0u;
        key[i * 4 + 1] = (pos + 1 < L) ? f2key(v4.y) : 0u;
        key[i * 4 + 2] = (pos + 2 < L) ? f2key(v4.z) : 0u;
        key[i * 4 + 3] = (pos + 3 < L) ? f2key(v4.w) : 0u;
    }

    // warp max key (== key of max valid value, by monotonicity; L>=1 always)
    unsigned kmax = 0;
    #pragma unroll
    for (int i = 0; i < 32; i++) kmax = max(kmax, key[i]);
    kmax = __reduce_max_sync(0xffffffffu, kmax);
    float m = key2f(kmax);

    // exact top-KNN threshold: binary search on key bits, early exit at count==KNN
    unsigned threshKey = 0;
    if (L > KNN) {
        unsigned lo = 0u, hi = kmax;
        while (lo < hi) {
            unsigned mid = (unsigned)((((unsigned long long)lo + (unsigned long long)hi + 1ull)) >> 1);
            unsigned c = 0;
            #pragma unroll
            for (int i = 0; i < 32; i++) c += (key[i] >= mid) ? 1u : 0u;
            c = __reduce_add_sync(0xffffffffu, c);
            if (c == KNN) { lo = mid; break; }    // {key>=mid} == exact top-KNN set
            if (c > KNN) lo = mid; else hi = mid - 1u;
        }
        threshKey = lo;
    }

    // softmax denominator over kept (values recovered bit-exactly from keys)
    bool noTrunc = (L <= KNN);
    float s = 0.f;
    #pragma unroll
    for (int i = 0; i < 8; i++) {
        int pos = i * 128 + lb;
        #pragma unroll
        for (int j = 0; j < 4; j++) {
            unsigned k = key[i * 4 + j];
            bool kept = (pos + j < L) && (noTrunc || k >= threshKey);
            if (kept) s += expf(key2f(k) - m);
        }
    }
    #pragma unroll
    for (int o = 16; o; o >>= 1) s += __shfl_xor_sync(0xffffffffu, s, o);
    float inv = 1.0f / s;
    float og = 1.0f - gw;

    // blend + store
    #pragma unroll
    for (int i = 0; i < 8; i++) {
        int pos = i * 128 + lb;
        float4 g4 = *(const float4*)&grow[pos];
        float gv[4] = {g4.x, g4.y, g4.z, g4.w};
        float4 o4;
        float* ov = (float*)&o4;
        #pragma unroll
        for (int j = 0; j < 4; j++) {
            unsigned k = key[i * 4 + j];
            bool kept = (pos + j < L) && (noTrunc || k >= threshKey);
            float e = kept ? expf(key2f(k) - m) : 0.f;
            ov[j] = gw * gv[j] + og * (e * inv);
        }
        *(float4*)&row[pos] = o4;
    }
}

// ---------------- LayerNorm over rows of DM=512 (elementwise_affine=False) ----------------
__global__ __launch_bounds__(128) void layernorm_k(const float* __restrict__ in,
                                                   float* __restrict__ out)
{
    __shared__ float sh[4];
    int row = blockIdx.x;
    int t = threadIdx.x;
    int lane = t & 31, w = t >> 5;
    const float* rin = in + (size_t)row * DM;
    float* rout = out + (size_t)row * DM;

    float4 v4 = *(const float4*)&rin[t * 4];
    float v[4] = {v4.x, v4.y, v4.z, v4.w};

    float s = v[0] + v[1] + v[2] + v[3];
    #pragma unroll
    for (int o = 16; o; o >>= 1) s += __shfl_xor_sync(0xffffffffu, s, o);
    if (lane == 0) sh[w] = s;
    __syncthreads();
    s = sh[0] + sh[1] + sh[2] + sh[3];
    float mean = s * (1.0f / DM);
    __syncthreads();

    float sq = 0.f;
    #pragma unroll
    for (int i = 0; i < 4; i++) { float d = v[i] - mean; sq += d * d; }
    #pragma unroll
    for (int o = 16; o; o >>= 1) sq += __shfl_xor_sync(0xffffffffu, sq, o);
    if (lane == 0) sh[w] = sq;
    __syncthreads();
    sq = sh[0] + sh[1] + sh[2] + sh[3];
    float var = sq * (1.0f / DM);
    float inv = rsqrtf(var + EPS);

    float4 o4;
    o4.x = (v[0] - mean) * inv; o4.y = (v[1] - mean) * inv;
    o4.z = (v[2] - mean) * inv; o4.w = (v[3] - mean) * inv;
    *(float4*)&rout[t * 4] = o4;
}

// ---------------- host-side helpers ----------------
template<int NTILE, int MINCTA>
static inline void gemm_t(const float* A, const float* B, float* C,
                          int M, int Nc, int Kc, int ldc,
                          long long sAo, long long sAi, long long sBo, long long sBi,
                          long long sCo, long long sCi, int Bo, int Bi,
                          const float* bias, long long sBias,
                          const float* resid, int ldr,
                          float alpha, int transB, int relu, int causal = 0)
{
    dim3 grid(Nc / NTILE, M / 128, Bo * Bi), block(256);
    size_t smem = (2 * 4096 + 2 * NTILE * 32) * sizeof(uint32_t);
    gemm_k<NTILE, MINCTA><<<grid, block, smem>>>(A, B, C, Nc, Kc, ldc, sAo, sAi, sBo, sBi,
                                                 sCo, sCi, Bi, bias, sBias, resid, ldr,
                                                 alpha, transB, relu, causal);
}

extern "C" void kernel_launch(void* const* d_in, const int* in_sizes, int n_in,
                              void* d_out, int out_size)
{
    (void)in_sizes; (void)n_in; (void)out_size;
    const float* z        = (const float*)d_in[0];
    const float* y        = (const float*)d_in[1];
    const float* graphDec = (const float*)d_in[2];
    const float* graphEnc = (const float*)d_in[3];
    const float* dec_Wk   = (const float*)d_in[4];
    const float* dec_bk   = (const float*)d_in[5];
    const float* dec_Wv   = (const float*)d_in[6];
    const float* dec_bv   = (const float*)d_in[7];
    const float* dec_Wo   = (const float*)d_in[8];
    const float* dec_bo   = (const float*)d_in[9];
    const float* enc_Wk   = (const float*)d_in[10];
    const float* enc_bk   = (const float*)d_in[11];
    const float* enc_Wq   = (const float*)d_in[12];
    const float* enc_bq   = (const float*)d_in[13];
    const float* enc_Wv   = (const float*)d_in[14];
    const float* enc_bv   = (const float*)d_in[15];
    const float* enc_Wo   = (const float*)d_in[16];
    const float* enc_bo   = (const float*)d_in[17];
    const float* fc_W1    = (const float*)d_in[18];
    const float* fc_b1    = (const float*)d_in[19];
    const float* fc_W2    = (const float*)d_in[20];
    const float* fc_b2    = (const float*)d_in[21];
    float* out = (float*)d_out;

    // allow 64KB dynamic smem for the wide-tile instantiation (host-side, idempotent)
    cudaFuncSetAttribute((const void*)gemm_k<128, 1>,
                         cudaFuncAttributeMaxDynamicSharedMemorySize, 66560);

    float* sc = nullptr;
    cudaGetSymbolAddress((void**)&sc, g_scratch);
    float* gdec = sc + OFF_GDEC;
    float* genc = sc + OFF_GENC;
    float* gK   = sc + OFF_K;
    float* gV   = sc + OFF_V;
    float* gQ   = sc + OFF_Q;
    float* gCtx = sc + OFF_CTX;
    float* gH   = sc + OFF_H;
    float* gH2  = sc + OFF_H2;
    float* gT   = sc + OFF_T;
    float* gAtt = sc + OFF_ATT;

    const int M = NB * SSQ;               // 4096
    const long long sKh = (long long)NB * SSQ * KD;  // per-head stride in K/V/Q
    const long long sKn = (long long)SSQ * KD;       // per-batch stride
    const long long sAh = (long long)NB * SSQ * SSQ; // att per-head
    const long long sAn = (long long)SSQ * SSQ;      // att per-batch
    const float inv_scale = 0.125f;       // 1/sqrt(64)
    const int ROWS = HH * NB * SSQ;       // 32768 attention rows

    // 0) graph row-softmax
    row_softmax_k<<<SSQ, 256>>>(graphDec, gdec);
    row_softmax_k<<<SSQ, 256>>>(graphEnc, genc);

    // ---------- stage 1: masked decoder self-attention on y ----------
    gemm_t<64, 2>(y, dec_Wk, gK, M, KD, DM, KD, 0, 0, (long long)DM * KD, 0, sKh, 0, HH, 1,
                  dec_bk, KD, nullptr, 0, 1.0f, 0, 0);
    gemm_t<64, 2>(y, dec_Wv, gV, M, VD, DM, VD, 0, 0, (long long)DM * VD, 0, sKh, 0, HH, 1,
                  dec_bv, VD, nullptr, 0, 1.0f, 0, 0);
    gemm_t<128, 1>(gK, gK, gAtt, SSQ, SSQ, KD, SSQ, sKh, sKn, sKh, sKn, sAh, sAn, HH, NB,
                   nullptr, 0, nullptr, 0, inv_scale, 1, 0, 1 /*causal skip*/);
    attn_post_k<<<ROWS / 8, 256>>>(gAtt, gdec, 1, 0.5f);
    gemm_t<64, 2>(gAtt, gV, gCtx, SSQ, VD, SSQ, DM, sAh, sAn, sKh, sKn, (long long)VD,
                  (long long)SSQ * DM, HH, NB, nullptr, 0, nullptr, 0, 1.0f, 0, 0);
    gemm_t<128, 1>(gCtx, dec_Wo, gH, M, DM, DM, DM, 0, 0, 0, 0, 0, 0, 1, 1,
                   dec_bo, 0, y, DM, 1.0f, 0, 0);
    layernorm_k<<<M, 128>>>(gH, gH);      // gH = h

    // ---------- stage 2: encoder-decoder attention (K,V from z, Q from h) ----------
    gemm_t<64, 2>(z, enc_Wk, gK, M, KD, DM, KD, 0, 0, (long long)DM * KD, 0, sKh, 0, HH, 1,
                  enc_bk, KD, nullptr, 0, 1.0f, 0, 0);
    gemm_t<64, 2>(z, enc_Wv, gV, M, VD, DM, VD, 0, 0, (long long)DM * VD, 0, sKh, 0, HH, 1,
                  enc_bv, VD, nullptr, 0, 1.0f, 0, 0);
    gemm_t<64, 2>(gH, enc_Wq, gQ, M, KD, DM, KD, 0, 0, (long long)DM * KD, 0, sKh, 0, HH, 1,
                  enc_bq, KD, nullptr, 0, 1.0f, 0, 0);
    gemm_t<128, 1>(gQ, gK, gAtt, SSQ, SSQ, KD, SSQ, sKh, sKn, sKh, sKn, sAh, sAn, HH, NB,
                   nullptr, 0, nullptr, 0, inv_scale, 1, 0);
    attn_post_k<<<ROWS / 8, 256>>>(gAtt, genc, 0, 0.5f);
    gemm_t<64, 2>(gAtt, gV, gCtx, SSQ, VD, SSQ, DM, sAh, sAn, sKh, sKn, (long long)VD,
                  (long long)SSQ * DM, HH, NB, nullptr, 0, nullptr, 0, 1.0f, 0, 0);
    gemm_t<128, 1>(gCtx, enc_Wo, gH2, M, DM, DM, DM, 0, 0, 0, 0, 0, 0, 1, 1,
                   enc_bo, 0, gH, DM, 1.0f, 0, 0);
    layernorm_k<<<M, 128>>>(gH2, gH2);    // gH2 = h2

    // ---------- stage 3: MLP ----------
    gemm_t<128, 1>(gH2, fc_W1, gT, M, FCD, DM, FCD, 0, 0, 0, 0, 0, 0, 1, 1,
                   fc_b1, 0, nullptr, 0, 1.0f, 0, 1);                 // relu
    gemm_t<128, 1>(gT, fc_W2, gH, M, DM, FCD, DM, 0, 0, 0, 0, 0, 0, 1, 1,
                   fc_b2, 0, gH2, DM, 1.0f, 0, 0);                    // + residual h2
    layernorm_k<<<M, 128>>>(gH, out);
}

// round 15
// speedup vs baseline: 1.1809x; 1.0826x over previous
#include <cuda_runtime.h>
#include <math_constants.h>
#include <cstdint>
#include <cstddef>

// Problem constants
#define HH 8
#define KD 64
#define VD 64
#define KNN 128
#define DM 512
#define FCD 2048
#define NB 4
#define SSQ 1024
#define EPS 1e-5f

// ---------------- scratch (single __device__ array, no allocations) ----------------
constexpr size_t OFF_GDEC = 0;
constexpr size_t OFF_GENC = OFF_GDEC + (size_t)SSQ * SSQ;
constexpr size_t OFF_K    = OFF_GENC + (size_t)SSQ * SSQ;           // dec K
constexpr size_t OFF_V    = OFF_K   + (size_t)HH * NB * SSQ * KD;   // dec V
constexpr size_t OFF_EK   = OFF_V   + (size_t)HH * NB * SSQ * VD;   // enc K
constexpr size_t OFF_EV   = OFF_EK  + (size_t)HH * NB * SSQ * KD;   // enc V
constexpr size_t OFF_Q    = OFF_EV  + (size_t)HH * NB * SSQ * VD;   // enc Q
constexpr size_t OFF_CTX  = OFF_Q   + (size_t)HH * NB * SSQ * KD;
constexpr size_t OFF_H    = OFF_CTX + (size_t)NB * SSQ * DM;
constexpr size_t OFF_H2   = OFF_H   + (size_t)NB * SSQ * DM;
constexpr size_t OFF_T    = OFF_H2  + (size_t)NB * SSQ * DM;
constexpr size_t OFF_ATT  = OFF_T   + (size_t)NB * SSQ * FCD;
constexpr size_t SCRATCH_TOTAL = OFF_ATT + (size_t)HH * NB * SSQ * SSQ;

__device__ float g_scratch[SCRATCH_TOTAL];

// ---------------- helpers ----------------
__device__ __forceinline__ uint32_t u2tf32(uint32_t x) {
    uint32_t o;
    asm("cvt.rna.tf32.f32 %0, %1;" : "=r"(o) : "f"(__uint_as_float(x)));
    return o;
}

__device__ __forceinline__ void mma_tf32v(float c[4],
                                          uint32_t a0, uint32_t a1, uint32_t a2, uint32_t a3,
                                          uint32_t b0, uint32_t b1)
{
    asm volatile(
        "mma.sync.aligned.m16n8k8.row.col.f32.tf32.tf32.f32 "
        "{%0,%1,%2,%3}, {%4,%5,%6,%7}, {%8,%9}, {%0,%1,%2,%3};"
        : "+f"(c[0]), "+f"(c[1]), "+f"(c[2]), "+f"(c[3])
        : "r"(a0), "r"(a1), "r"(a2), "r"(a3),
          "r"(b0), "r"(b1));
}

__device__ __forceinline__ void ldsm4(uint32_t& d0, uint32_t& d1, uint32_t& d2, uint32_t& d3,
                                      uint32_t addr)
{
    asm volatile("ldmatrix.sync.aligned.m8n8.x4.shared.b16 {%0,%1,%2,%3}, [%4];"
                 : "=r"(d0), "=r"(d1), "=r"(d2), "=r"(d3) : "r"(addr));
}

#define CP16(dst, src) asm volatile("cp.async.cg.shared.global [%0], [%1], 16;" :: "r"(dst), "l"(src))
#define CP4(dst, src)  asm volatile("cp.async.ca.shared.global [%0], [%1], 4;"  :: "r"(dst), "l"(src))
#define CP_COMMIT()    asm volatile("cp.async.commit_group;" ::: "memory")
#define CP_WAIT2()     asm volatile("cp.async.wait_group 2;" ::: "memory")
#define CP_WAIT0()     asm volatile("cp.async.wait_group 0;" ::: "memory")

// ---------------- batched TF32 GEMM: cp.async 4-stage pipeline + SW128 + ldmatrix ------
// C = alpha*A@B(^T) [+bias][relu][+resid]
// Block tile 128(M) x 64(N), K-tile 32, 256 threads = 8 warps (4x2), warp tile 32x32.
// Raw fp32 in smem; cvt.rna.tf32 applied post-ldmatrix (bit-identical numerics).
// multi=1: 4-group projection mode — zo>>3 selects weight {B,B1,B2,B3}, bias
// {bias,bias1,bias2,bias3}, and A (groups 0,1) vs A2 (groups 2,3); C += z*sCo.
// causal=1: skip blocks entirely above the diagonal.
#define STAGES 4
#define STAGE_WORDS 6144            // 4096 A + 2048 B
#define STAGE_BYTES 24576
#define A_BYTES 16384

__global__ __launch_bounds__(256, 2) void gemm_k(
    const float* __restrict__ A, const float* __restrict__ A2,
    const float* __restrict__ B, const float* __restrict__ B1,
    const float* __restrict__ B2, const float* __restrict__ B3,
    float* __restrict__ C,
    int Nc, int Kc, int ldc,
    long long sAo, long long sAi, long long sBo, long long sBi,
    long long sCo, long long sCi, int Bi,
    const float* __restrict__ bias, const float* __restrict__ bias1,
    const float* __restrict__ bias2, const float* __restrict__ bias3,
    long long sBias,
    const float* __restrict__ resid, int ldr,
    float alpha, int transB, int relu, int causal, int multi)
{
    extern __shared__ uint32_t smem_u[];

    int bn0 = blockIdx.x * 64;
    int bm0 = blockIdx.y * 128;
    if (causal && bn0 >= bm0 + 128) return;

    int z = blockIdx.z;
    const float* biasp;
    if (multi) {
        int grp = z >> 3, h = z & 7;
        if (grp >= 2) A = A2;
        const float* Bsel = (grp == 0) ? B : (grp == 1) ? B1 : (grp == 2) ? B2 : B3;
        const float* bsel = (grp == 0) ? bias : (grp == 1) ? bias1 : (grp == 2) ? bias2 : bias3;
        B = Bsel + (size_t)h * sBi;
        biasp = bsel + (size_t)h * sBias;
        C += (size_t)z * sCo;
    } else {
        int zo = z / Bi, zi = z - zo * Bi;
        A += (size_t)zo * sAo + (size_t)zi * sAi;
        B += (size_t)zo * sBo + (size_t)zi * sBi;
        C += (size_t)zo * sCo + (size_t)zi * sCi;
        biasp = bias ? (bias + (size_t)zo * sBias) : nullptr;
    }

    int t = threadIdx.x;
    int lane = t & 31, w = t >> 5;
    int wm = w >> 1, wn = w & 1;
    int gid = lane >> 2, tg = lane & 3;

    // ---- loader mappings (byte offsets within a stage) ----
    int a_row[4]; uint32_t aStB[4];
    #pragma unroll
    for (int i = 0; i < 4; i++) {
        int idx = t + i * 256;
        a_row[i] = idx >> 3; int kq = idx & 7;
        aStB[i] = (uint32_t)((a_row[i] * 32 + ((kq ^ (a_row[i] & 7)) << 2)) * 4);
    }
    int bt_row[2]; uint32_t btStB[2];
    #pragma unroll
    for (int i = 0; i < 2; i++) {
        int idx = t + i * 256;
        bt_row[i] = idx >> 3; int kq = idx & 7;
        btStB[i] = (uint32_t)((bt_row[i] * 32 + ((kq ^ (bt_row[i] & 7)) << 2)) * 4);
    }
    int bn_n[2], bn_ks[2]; uint32_t bnStB[2];
    #pragma unroll
    for (int i = 0; i < 2; i++) {
        int idx = t + i * 256;
        bn_n[i] = idx & 63; bn_ks[i] = idx >> 6;
        bnStB[i] = (uint32_t)((bn_n[i] * 32 + ((bn_ks[i] ^ (bn_n[i] & 7)) << 2)) * 4);
    }

    // ---- auto-incrementing global source pointers ----
    const float4* paP[4];
    #pragma unroll
    for (int i = 0; i < 4; i++)
        paP[i] = (const float4*)(A + (size_t)(bm0 + a_row[i]) * Kc) + ((t + i * 256) & 7);
    const float4* pbtP[2];
    const float*  pbnP[2];
    if (transB) {
        #pragma unroll
        for (int i = 0; i < 2; i++)
            pbtP[i] = (const float4*)(B + (size_t)(bn0 + bt_row[i]) * Kc) + ((t + i * 256) & 7);
    } else {
        #pragma unroll
        for (int i = 0; i < 2; i++)
            pbnP[i] = B + (size_t)(bn_ks[i] * 4) * Nc + bn0 + bn_n[i];
    }
    long long bnStep = (long long)Nc * 32;

    // ---- ldmatrix lane constants + per-k8 relative byte offsets ----
    int r8 = lane & 7;
    int im = lane >> 3;
    int rowA0 = wm * 32 + r8 + 8 * (im & 1);
    int c1A = im >> 1;
    int rowB0 = wn * 32 + r8 + 8 * (im >> 1);
    int c1B = im & 1;

    uint32_t offA[4], offB[4];
    #pragma unroll
    for (int ks = 0; ks < 4; ks++) {
        offA[ks] = (uint32_t)(rowA0 * 128 + (((2 * ks + c1A) ^ r8) << 4));
        offB[ks] = (uint32_t)(rowB0 * 128 + (((2 * ks + c1B) ^ r8) << 4));
    }

    uint32_t smemB = (uint32_t)__cvta_generic_to_shared(smem_u);

    float acc[2][4][4] = {};

    auto issue_tile = [&](int tt) {
        uint32_t aBase = smemB + (uint32_t)((tt & 3) * STAGE_BYTES);
        uint32_t bBase = aBase + A_BYTES;
        #pragma unroll
        for (int i = 0; i < 4; i++) { CP16(aBase + aStB[i], paP[i]); paP[i] += 8; }
        if (transB) {
            #pragma unroll
            for (int i = 0; i < 2; i++) { CP16(bBase + btStB[i], pbtP[i]); pbtP[i] += 8; }
        } else {
            #pragma unroll
            for (int i = 0; i < 2; i++) {
                #pragma unroll
                for (int j = 0; j < 4; j++)
                    CP4(bBase + bnStB[i] + (uint32_t)(j * 4), pbnP[i] + (size_t)j * Nc);
                pbnP[i] += bnStep;
            }
        }
    };

    int nT = Kc >> 5;

    // ---- prologue: issue up to 3 tiles ----
    #pragma unroll
    for (int p = 0; p < 3; p++) {
        if (p < nT) issue_tile(p);
        CP_COMMIT();
    }

    for (int tt = 0; tt < nT; tt++) {
        CP_WAIT2();          // tile tt arrived (<=2 groups pending)
        __syncthreads();     // all warps see tile tt; prev compute done before reissue
        int ft = tt + 3;
        if (ft < nT) issue_tile(ft);
        CP_COMMIT();

        uint32_t baseA = smemB + (uint32_t)((tt & 3) * STAGE_BYTES);
        uint32_t baseB = baseA + A_BYTES;
        #pragma unroll
        for (int ks = 0; ks < 4; ks++) {
            uint32_t aAddr = baseA + offA[ks];
            uint32_t bAddr = baseB + offB[ks];
            uint32_t af0[4], af1[4], bq0[4], bq1[4];
            ldsm4(af0[0], af0[1], af0[2], af0[3], aAddr);
            ldsm4(af1[0], af1[1], af1[2], af1[3], aAddr + 2048);
            ldsm4(bq0[0], bq0[1], bq0[2], bq0[3], bAddr);
            ldsm4(bq1[0], bq1[1], bq1[2], bq1[3], bAddr + 2048);
            #pragma unroll
            for (int j = 0; j < 4; j++) {
                af0[j] = u2tf32(af0[j]); af1[j] = u2tf32(af1[j]);
                bq0[j] = u2tf32(bq0[j]); bq1[j] = u2tf32(bq1[j]);
            }
            mma_tf32v(acc[0][0], af0[0], af0[1], af0[2], af0[3], bq0[0], bq0[1]);
            mma_tf32v(acc[0][1], af0[0], af0[1], af0[2], af0[3], bq0[2], bq0[3]);
            mma_tf32v(acc[0][2], af0[0], af0[1], af0[2], af0[3], bq1[0], bq1[1]);
            mma_tf32v(acc[0][3], af0[0], af0[1], af0[2], af0[3], bq1[2], bq1[3]);
            mma_tf32v(acc[1][0], af1[0], af1[1], af1[2], af1[3], bq0[0], bq0[1]);
            mma_tf32v(acc[1][1], af1[0], af1[1], af1[2], af1[3], bq0[2], bq0[3]);
            mma_tf32v(acc[1][2], af1[0], af1[1], af1[2], af1[3], bq1[0], bq1[1]);
            mma_tf32v(acc[1][3], af1[0], af1[1], af1[2], af1[3], bq1[2], bq1[3]);
        }
    }
    CP_WAIT0();

    // ---- epilogue ----
    int mb = wm * 32, nb = wn * 32;
    #pragma unroll
    for (int mi = 0; mi < 2; mi++) {
        int r0 = bm0 + mb + mi * 16 + gid;
        #pragma unroll
        for (int nj = 0; nj < 4; nj++) {
            int cc = bn0 + nb + nj * 8 + 2 * tg;
            float b0 = 0.f, b1 = 0.f;
            if (biasp) { b0 = biasp[cc]; b1 = biasp[cc + 1]; }
            #pragma unroll
            for (int half = 0; half < 2; half++) {
                int row = r0 + half * 8;
                float vx = acc[mi][nj][half * 2 + 0] * alpha + b0;
                float vy = acc[mi][nj][half * 2 + 1] * alpha + b1;
                if (relu) { vx = fmaxf(vx, 0.f); vy = fmaxf(vy, 0.f); }
                if (resid) {
                    float2 r = *(const float2*)&resid[(size_t)row * ldr + cc];
                    vx += r.x; vy += r.y;
                }
                float2 o; o.x = vx; o.y = vy;
                *(float2*)&C[(size_t)row * ldc + cc] = o;
            }
        }
    }
}

// ---------------- row softmax (graph preprocessing), rows of length SSQ ----------------
__global__ __launch_bounds__(256) void row_softmax_k(const float* __restrict__ in,
                                                     float* __restrict__ out)
{
    __shared__ float sh[8];
    int row = blockIdx.x;
    int t = threadIdx.x;
    int lane = t & 31, w = t >> 5;
    const float* rin = in + (size_t)row * SSQ;
    float* rout = out + (size_t)row * SSQ;

    float4 v4 = *(const float4*)&rin[t * 4];
    float v[4] = {v4.x, v4.y, v4.z, v4.w};

    float m = fmaxf(fmaxf(v[0], v[1]), fmaxf(v[2], v[3]));
    #pragma unroll
    for (int o = 16; o; o >>= 1) m = fmaxf(m, __shfl_xor_sync(0xffffffffu, m, o));
    if (lane == 0) sh[w] = m;
    __syncthreads();
    m = sh[0];
    #pragma unroll
    for (int i = 1; i < 8; i++) m = fmaxf(m, sh[i]);
    __syncthreads();

    float e[4]; float s = 0.f;
    #pragma unroll
    for (int i = 0; i < 4; i++) { e[i] = expf(v[i] - m); s += e[i]; }
    #pragma unroll
    for (int o = 16; o; o >>= 1) s += __shfl_xor_sync(0xffffffffu, s, o);
    if (lane == 0) sh[w] = s;
    __syncthreads();
    s = 0.f;
    #pragma unroll
    for (int i = 0; i < 8; i++) s += sh[i];
    float inv = 1.0f / s;
    float4 o4;
    o4.x = e[0] * inv; o4.y = e[1] * inv; o4.z = e[2] * inv; o4.w = e[3] * inv;
    *(float4*)&rout[t * 4] = o4;
}

// ---------------- fused: causal mask + exact top-KNN + softmax + graph blend ----------
// One WARP per attention row: keys in 32 regs, REDUX reductions, zero barriers.
__device__ __forceinline__ unsigned f2key(float f) {
    unsigned u = __float_as_uint(f);
    return (u & 0x80000000u) ? ~u : (u | 0x80000000u);
}
__device__ __forceinline__ float key2f(unsigned k) {
    unsigned u = (k & 0x80000000u) ? (k & 0x7fffffffu) : ~k;
    return __uint_as_float(u);
}

__global__ __launch_bounds__(256) void attn_post_k(float* __restrict__ att,
                                                   const float* __restrict__ graph,
                                                   int masked, float gw)
{
    int wid = threadIdx.x >> 5, lane = threadIdx.x & 31;
    int rowIdx = blockIdx.x * 8 + wid;            // [0, HH*NB*SSQ)
    int q = rowIdx & (SSQ - 1);
    float* row = att + (size_t)rowIdx * SSQ;
    const float* grow = graph + (size_t)q * SSQ;
    int L = masked ? (q + 1) : SSQ;
    int lb = lane * 4;

    unsigned key[32];
    #pragma unroll
    for (int i = 0; i < 8; i++) {
        int pos = i * 128 + lb;
        float4 v4 = *(const float4*)&row[pos];
        key[i * 4 + 0] = (pos + 0 < L) ? f2key(v4.x) : 0u;
        key[i * 4 + 1] = (pos + 1 < L) ? f2key(v4.y) : 0u;
        key[i * 4 + 2] = (pos + 2 < L) ? f2key(v4.z) : 0u;
        key[i * 4 + 3] = (pos + 3 < L) ? f2key(v4.w) : 0u;
    }

    unsigned kmax = 0;
    #pragma unroll
    for (int i = 0; i < 32; i++) kmax = max(kmax, key[i]);
    kmax = __reduce_max_sync(0xffffffffu, kmax);
    float m = key2f(kmax);

    unsigned threshKey = 0;
    if (L > KNN) {
        unsigned lo = 0u, hi = kmax;
        while (lo < hi) {
            unsigned mid = (unsigned)((((unsigned long long)lo + (unsigned long long)hi + 1ull)) >> 1);
            unsigned c = 0;
            #pragma unroll
            for (int i = 0; i < 32; i++) c += (key[i] >= mid) ? 1u : 0u;
            c = __reduce_add_sync(0xffffffffu, c);
            if (c == KNN) { lo = mid; break; }
            if (c > KNN) lo = mid; else hi = mid - 1u;
        }
        threshKey = lo;
    }

    bool noTrunc = (L <= KNN);
    float s = 0.f;
    #pragma unroll
    for (int i = 0; i < 8; i++) {
        int pos = i * 128 + lb;
        #pragma unroll
        for (int j = 0; j < 4; j++) {
            unsigned k = key[i * 4 + j];
            bool kept = (pos + j < L) && (noTrunc || k >= threshKey);
            if (kept) s += expf(key2f(k) - m);
        }
    }
    #pragma unroll
    for (int o = 16; o; o >>= 1) s += __shfl_xor_sync(0xffffffffu, s, o);
    float inv = 1.0f / s;
    float og = 1.0f - gw;

    #pragma unroll
    for (int i = 0; i < 8; i++) {
        int pos = i * 128 + lb;
        float4 g4 = *(const float4*)&grow[pos];
        float gv[4] = {g4.x, g4.y, g4.z, g4.w};
        float4 o4;
        float* ov = (float*)&o4;
        #pragma unroll
        for (int j = 0; j < 4; j++) {
            unsigned k = key[i * 4 + j];
            bool kept = (pos + j < L) && (noTrunc || k >= threshKey);
            float e = kept ? expf(key2f(k) - m) : 0.f;
            ov[j] = gw * gv[j] + og * (e * inv);
        }
        *(float4*)&row[pos] = o4;
    }
}

// ---------------- LayerNorm over rows of DM=512 (elementwise_affine=False) ----------------
__global__ __launch_bounds__(128) void layernorm_k(const float* __restrict__ in,
                                                   float* __restrict__ out)
{
    __shared__ float sh[4];
    int row = blockIdx.x;
    int t = threadIdx.x;
    int lane = t & 31, w = t >> 5;
    const float* rin = in + (size_t)row * DM;
    float* rout = out + (size_t)row * DM;

    float4 v4 = *(const float4*)&rin[t * 4];
    float v[4] = {v4.x, v4.y, v4.z, v4.w};

    float s = v[0] + v[1] + v[2] + v[3];
    #pragma unroll
    for (int o = 16; o; o >>= 1) s += __shfl_xor_sync(0xffffffffu, s, o);
    if (lane == 0) sh[w] = s;
    __syncthreads();
    s = sh[0] + sh[1] + sh[2] + sh[3];
    float mean = s * (1.0f / DM);
    __syncthreads();

    float sq = 0.f;
    #pragma unroll
    for (int i = 0; i < 4; i++) { float d = v[i] - mean; sq += d * d; }
    #pragma unroll
    for (int o = 16; o; o >>= 1) sq += __shfl_xor_sync(0xffffffffu, sq, o);
    if (lane == 0) sh[w] = sq;
    __syncthreads();
    sq = sh[0] + sh[1] + sh[2] + sh[3];
    float var = sq * (1.0f / DM);
    float inv = rsqrtf(var + EPS);

    float4 o4;
    o4.x = (v[0] - mean) * inv; o4.y = (v[1] - mean) * inv;
    o4.z = (v[2] - mean) * inv; o4.w = (v[3] - mean) * inv;
    *(float4*)&rout[t * 4] = o4;
}

// ---------------- host-side helpers ----------------
static const size_t GEMM_SMEM = STAGES * STAGE_BYTES;   // 98304

static inline void gemm(const float* A, const float* B, float* C,
                        int M, int Nc, int Kc, int ldc,
                        long long sAo, long long sAi, long long sBo, long long sBi,
                        long long sCo, long long sCi, int Bo, int Bi,
                        const float* bias, long long sBias,
                        const float* resid, int ldr,
                        float alpha, int transB, int relu, int causal = 0)
{
    dim3 grid(Nc / 64, M / 128, Bo * Bi), block(256);
    gemm_k<<<grid, block, GEMM_SMEM>>>(A, nullptr, B, nullptr, nullptr, nullptr, C,
                                       Nc, Kc, ldc, sAo, sAi, sBo, sBi, sCo, sCi, Bi,
                                       bias, nullptr, nullptr, nullptr, sBias,
                                       resid, ldr, alpha, transB, relu, causal, 0);
}

// merged 4-group projections: groups {B,bias}(A), {B1,bias1}(A), {B2,bias2}(A2), {B3,bias3}(A2)
static inline void gemm_proj4(const float* A, const float* A2,
                              const float* B0, const float* B1,
                              const float* B2, const float* B3,
                              float* C, int M,
                              const float* b0, const float* b1,
                              const float* b2, const float* b3)
{
    dim3 grid(1, M / 128, 4 * HH), block(256);
    gemm_k<<<grid, block, GEMM_SMEM>>>(A, A2, B0, B1, B2, B3, C,
                                       KD, DM, KD,
                                       0, 0, 0, (long long)DM * KD,
                                       (long long)NB * SSQ * KD, 0, 1,
                                       b0, b1, b2, b3, KD,
                                       nullptr, 0, 1.0f, 0, 0, 0, 1);
}

extern "C" void kernel_launch(void* const* d_in, const int* in_sizes, int n_in,
                              void* d_out, int out_size)
{
    (void)in_sizes; (void)n_in; (void)out_size;
    const float* z        = (const float*)d_in[0];
    const float* y        = (const float*)d_in[1];
    const float* graphDec = (const float*)d_in[2];
    const float* graphEnc = (const float*)d_in[3];
    const float* dec_Wk   = (const float*)d_in[4];
    const float* dec_bk   = (const float*)d_in[5];
    const float* dec_Wv   = (const float*)d_in[6];
    const float* dec_bv   = (const float*)d_in[7];
    const float* dec_Wo   = (const float*)d_in[8];
    const float* dec_bo   = (const float*)d_in[9];
    const float* enc_Wk   = (const float*)d_in[10];
    const float* enc_bk   = (const float*)d_in[11];
    const float* enc_Wq   = (const float*)d_in[12];
    const float* enc_bq   = (const float*)d_in[13];
    const float* enc_Wv   = (const float*)d_in[14];
    const float* enc_bv   = (const float*)d_in[15];
    const float* enc_Wo   = (const float*)d_in[16];
    const float* enc_bo   = (const float*)d_in[17];
    const float* fc_W1    = (const float*)d_in[18];
    const float* fc_b1    = (const float*)d_in[19];
    const float* fc_W2    = (const float*)d_in[20];
    const float* fc_b2    = (const float*)d_in[21];
    float* out = (float*)d_out;

    // opt-in to 96KB dynamic smem (host-side, idempotent, capture-safe)
    cudaFuncSetAttribute(gemm_k, cudaFuncAttributeMaxDynamicSharedMemorySize,
                         (int)GEMM_SMEM);

    float* sc = nullptr;
    cudaGetSymbolAddress((void**)&sc, g_scratch);
    float* gdec = sc + OFF_GDEC;
    float* genc = sc + OFF_GENC;
    float* gK   = sc + OFF_K;
    float* gV   = sc + OFF_V;
    float* eK   = sc + OFF_EK;
    float* eV   = sc + OFF_EV;
    float* gQ   = sc + OFF_Q;
    float* gCtx = sc + OFF_CTX;
    float* gH   = sc + OFF_H;
    float* gH2  = sc + OFF_H2;
    float* gT   = sc + OFF_T;
    float* gAtt = sc + OFF_ATT;

    const int M = NB * SSQ;               // 4096
    const long long sKh = (long long)NB * SSQ * KD;  // per-head stride in K/V/Q
    const long long sKn = (long long)SSQ * KD;       // per-batch stride
    const long long sAh = (long long)NB * SSQ * SSQ; // att per-head
    const long long sAn = (long long)SSQ * SSQ;      // att per-batch
    const float inv_scale = 0.125f;       // 1/sqrt(64)
    const int ROWS = HH * NB * SSQ;       // 32768 attention rows

    // 0) graph row-softmax
    row_softmax_k<<<SSQ, 256>>>(graphDec, gdec);
    row_softmax_k<<<SSQ, 256>>>(graphEnc, genc);

    // merged projections: dec K/V from y, enc K/V from z -> gK,gV,eK,eV (contiguous)
    gemm_proj4(y, z, dec_Wk, dec_Wv, enc_Wk, enc_Wv, gK,
               M, dec_bk, dec_bv, enc_bk, enc_bv);

    // ---------- stage 1: masked decoder self-attention on y ----------
    gemm(gK, gK, gAtt, SSQ, SSQ, KD, SSQ, sKh, sKn, sKh, sKn, sAh, sAn, HH, NB,
         nullptr, 0, nullptr, 0, inv_scale, 1, 0, 1 /*causal skip*/);
    attn_post_k<<<ROWS / 8, 256>>>(gAtt, gdec, 1, 0.5f);
    gemm(gAtt, gV, gCtx, SSQ, VD, SSQ, DM, sAh, sAn, sKh, sKn, (long long)VD,
         (long long)SSQ * DM, HH, NB, nullptr, 0, nullptr, 0, 1.0f, 0, 0);
    gemm(gCtx, dec_Wo, gH, M, DM, DM, DM, 0, 0, 0, 0, 0, 0, 1, 1,
         dec_bo, 0, y, DM, 1.0f, 0, 0);
    layernorm_k<<<M, 128>>>(gH, gH);      // gH = h

    // ---------- stage 2: encoder-decoder attention (K,V from z, Q from h) ----------
    gemm(gH, enc_Wq, gQ, M, KD, DM, KD, 0, 0, (long long)DM * KD, 0, sKh, 0, HH, 1,
         enc_bq, KD, nullptr, 0, 1.0f, 0, 0);
    gemm(gQ, eK, gAtt, SSQ, SSQ, KD, SSQ, sKh, sKn, sKh, sKn, sAh, sAn, HH, NB,
         nullptr, 0, nullptr, 0, inv_scale, 1, 0);
    attn_post_k<<<ROWS / 8, 256>>>(gAtt, genc, 0, 0.5f);
    gemm(gAtt, eV, gCtx, SSQ, VD, SSQ, DM, sAh, sAn, sKh, sKn, (long long)VD,
         (long long)SSQ * DM, HH, NB, nullptr, 0, nullptr, 0, 1.0f, 0, 0);
    gemm(gCtx, enc_Wo, gH2, M, DM, DM, DM, 0, 0, 0, 0, 0, 0, 1, 1,
         enc_bo, 0, gH, DM, 1.0f, 0, 0);
    layernorm_k<<<M, 128>>>(gH2, gH2);    // gH2 = h2

    // ---------- stage 3: MLP ----------
    gemm(gH2, fc_W1, gT, M, FCD, DM, FCD, 0, 0, 0, 0, 0, 0, 1, 1,
         fc_b1, 0, nullptr, 0, 1.0f, 0, 1);                 // relu
    gemm(gT, fc_W2, gH, M, DM, FCD, DM, 0, 0, 0, 0, 0, 0, 1, 1,
         fc_b2, 0, gH2, DM, 1.0f, 0, 0);                    // + residual h2
    layernorm_k<<<M, 128>>>(gH, out);
}